// round 1
// baseline (speedup 1.0000x reference)
#include <cuda_runtime.h>
#include <cuda_bf16.h>
#include <math.h>

// Problem constants
#define G_   64
#define T_   10
#define IN_  256
#define H_   256
#define H4_  1024

// Output offsets (tuple flattened: gamma, beta, delta, hN, cN)
#define OFF_GAMMA 0
#define OFF_BETA  640
#define OFF_DELTA 164480
#define OFF_HN    328320
#define OFF_CN    361088

// Scratch (device globals; no allocation allowed)
__device__ float g_xg  [G_ * T_ * H4_];  // gate pre-activations (reused layer0/layer1)
__device__ float g_h1  [G_ * T_ * H_];   // layer0 hidden over time
__device__ float g_h2  [G_ * T_ * H_];   // layer1 hidden over time
__device__ float g_fc  [G_ * T_ * H_];   // per-group linear output
__device__ float g_lin1[G_ * T_ * H_];   // shared head 1 output (softmax input)

__device__ __forceinline__ float sigf(float x) { return 1.0f / (1.0f + expf(-x)); }

// ---------------------------------------------------------------------------
// Projection kernel: Y[g,t,k] = sum_i W[g,k,i] * x[g,t,i] + bA[g,k] (+ bB[g,k])
// xmode: 0 -> Xext with layout [T, G, 256]; 1 -> g_h1 [G,T,256]; 2 -> g_h2
// omode: 0 -> g_xg (rows=1024); 1 -> g_fc (rows=256)
// Grid: G * (rows/256) blocks, 256 threads. Warp handles 32 rows, loops T.
// ---------------------------------------------------------------------------
__global__ void proj_kernel(const float* __restrict__ W,
                            const float* __restrict__ bA,
                            const float* __restrict__ bB,
                            const float* __restrict__ Xext,
                            int xmode, int rows, int omode)
{
    __shared__ float xs[T_ * 256];  // [t][i]
    const int bpg   = rows >> 8;                 // blocks per group
    const int g     = blockIdx.x / bpg;
    const int kbase = (blockIdx.x % bpg) << 8;
    const int tid   = threadIdx.x;
    const int lane  = tid & 31;
    const int warp  = tid >> 5;

    // Load x[g, :, :] into shared
    if (xmode == 0) {
        for (int e = tid; e < T_ * 256; e += 256) {
            int t = e >> 8, i = e & 255;
            xs[e] = Xext[((size_t)t * G_ + g) * 256 + i];
        }
    } else {
        const float* hp = (xmode == 1 ? g_h1 : g_h2) + (size_t)g * T_ * 256;
        for (int e = tid; e < T_ * 256; e += 256) xs[e] = hp[e];
    }
    __syncthreads();

    const float4* xs4 = (const float4*)xs;  // [t][64]
    float* Y = (omode == 0 ? g_xg : g_fc);
    const size_t ybase = (size_t)g * T_ * rows;

    for (int r = 0; r < 32; r++) {
        const int k = kbase + warp * 32 + r;
        const float4* wr = (const float4*)(W + ((size_t)g * rows + k) * 256);
        float4 a0 = wr[lane];
        float4 a1 = wr[lane + 32];
        float bias = 0.0f;
        if (lane == 0) {
            bias = bA[(size_t)g * rows + k];
            if (bB) bias += bB[(size_t)g * rows + k];
        }
        #pragma unroll
        for (int t = 0; t < T_; t++) {
            float4 x0 = xs4[t * 64 + lane];
            float4 x1 = xs4[t * 64 + lane + 32];
            float s = a0.x * x0.x + a0.y * x0.y + a0.z * x0.z + a0.w * x0.w
                    + a1.x * x1.x + a1.y * x1.y + a1.z * x1.z + a1.w * x1.w;
            #pragma unroll
            for (int o = 16; o > 0; o >>= 1) s += __shfl_xor_sync(0xffffffffu, s, o);
            if (lane == 0) Y[ybase + (size_t)t * rows + k] = s + bias;
        }
    }
}

// ---------------------------------------------------------------------------
// LSTM recurrence for one layer. Grid: 64 blocks (one per group), 1024 threads.
// Thread k owns gate row k. Gate order (PyTorch): i, f, g, o.
// ---------------------------------------------------------------------------
__global__ __launch_bounds__(1024, 1)
void lstm_rec_kernel(const float* __restrict__ Whh, int layer, float* __restrict__ out)
{
    __shared__ float h_s[256];
    __shared__ float gate_s[1024];

    const int g = blockIdx.x;
    const int k = threadIdx.x;

    const float* xg   = g_xg + (size_t)g * T_ * H4_;
    float*       hdst = (layer == 0 ? g_h1 : g_h2) + (size_t)g * T_ * H_;
    const float4* wrow = (const float4*)(Whh + ((size_t)g * H4_ + k) * 256);
    const float4* h4   = (const float4*)h_s;

    float c = 0.0f;
    if (k < 256) h_s[k] = 0.0f;
    __syncthreads();

    for (int t = 0; t < T_; t++) {
        float acc = xg[(size_t)t * H4_ + k];
        if (t > 0) {
            #pragma unroll 8
            for (int i = 0; i < 64; i++) {
                float4 w = wrow[i];
                float4 h = h4[i];
                acc += w.x * h.x + w.y * h.y + w.z * h.z + w.w * h.w;
            }
        }
        __syncthreads();  // protect h_s before overwrite (t>0 readers done)
        gate_s[k] = acc;
        __syncthreads();
        if (k < 256) {
            float ig = gate_s[k];
            float fg = gate_s[k + 256];
            float gg = gate_s[k + 512];
            float og = gate_s[k + 768];
            c = sigf(fg) * c + sigf(ig) * tanhf(gg);
            float h = sigf(og) * tanhf(c);
            h_s[k] = h;
            hdst[(size_t)t * H_ + k] = h;
        }
        __syncthreads();
    }

    if (k < 256) {
        out[OFF_HN + (size_t)g * 512 + layer * 256 + k] = h_s[k];
        out[OFF_CN + (size_t)g * 512 + layer * 256 + k] = c;
    }
}

// ---------------------------------------------------------------------------
// Shared heads: lin1 = fc @ W1^T + b1 ; beta = softplus(fc @ W2^T + b2)
// gamma = lin1 @ Wd^T + bd. Grid: 80 blocks = (gt in 0..7) x (t in 0..9).
// Block handles 8 groups x 256 outputs for one t. Thread = output j.
// ---------------------------------------------------------------------------
__global__ void heads_kernel(const float* __restrict__ W1, const float* __restrict__ b1,
                             const float* __restrict__ W2, const float* __restrict__ b2,
                             const float* __restrict__ Wd, const float* __restrict__ bd,
                             float* __restrict__ out)
{
    __shared__ float fcs[8][256];
    __shared__ float red[256];

    const int t  = blockIdx.x % 10;
    const int g0 = (blockIdx.x / 10) * 8;
    const int j  = threadIdx.x;

    for (int gg = 0; gg < 8; gg++)
        fcs[gg][j] = g_fc[((size_t)(g0 + gg) * T_ + t) * 256 + j];
    __syncthreads();

    const float4* w1r = (const float4*)(W1 + (size_t)j * 256);
    const float4* w2r = (const float4*)(W2 + (size_t)j * 256);
    const float4 (*f4)[64] = (const float4 (*)[64])fcs;

    float acc1[8], acc2[8];
    #pragma unroll
    for (int gg = 0; gg < 8; gg++) { acc1[gg] = b1[j]; acc2[gg] = b2[j]; }

    #pragma unroll 4
    for (int i4 = 0; i4 < 64; i4++) {
        float4 w1 = w1r[i4];
        float4 w2 = w2r[i4];
        #pragma unroll
        for (int gg = 0; gg < 8; gg++) {
            float4 f = f4[gg][i4];
            acc1[gg] += w1.x * f.x + w1.y * f.y + w1.z * f.z + w1.w * f.w;
            acc2[gg] += w2.x * f.x + w2.y * f.y + w2.z * f.z + w2.w * f.w;
        }
    }

    const float wd = Wd[j];
    #pragma unroll
    for (int gg = 0; gg < 8; gg++) {
        const size_t idx = ((size_t)(g0 + gg) * T_ + t) * 256 + j;
        g_lin1[idx] = acc1[gg];
        float x = acc2[gg];
        out[OFF_BETA + idx] = (x > 20.0f) ? x : log1pf(expf(x));
    }

    // gamma: block-reduce dot(lin1_row, Wd) per group
    for (int gg = 0; gg < 8; gg++) {
        red[j] = acc1[gg] * wd;
        __syncthreads();
        #pragma unroll
        for (int s = 128; s > 0; s >>= 1) {
            if (j < s) red[j] += red[j + s];
            __syncthreads();
        }
        if (j == 0) out[OFF_GAMMA + (size_t)(g0 + gg) * T_ + t] = red[0] + bd[0];
        __syncthreads();
    }
}

// ---------------------------------------------------------------------------
// Softmax over the group axis: delta[g,t,j] = softmax_g(lin1[g,t,j])
// Grid: 10 blocks (one per t), 256 threads (one per j).
// ---------------------------------------------------------------------------
__global__ void softmax_kernel(float* __restrict__ out)
{
    const int t = blockIdx.x;
    const int j = threadIdx.x;

    float v[G_];
    float m = -1e30f;
    #pragma unroll
    for (int g = 0; g < G_; g++) {
        v[g] = g_lin1[((size_t)g * T_ + t) * 256 + j];
        m = fmaxf(m, v[g]);
    }
    float s = 0.0f;
    #pragma unroll
    for (int g = 0; g < G_; g++) { v[g] = expf(v[g] - m); s += v[g]; }
    const float inv = 1.0f / s;
    #pragma unroll
    for (int g = 0; g < G_; g++)
        out[OFF_DELTA + ((size_t)g * T_ + t) * 256 + j] = v[g] * inv;
}

// ---------------------------------------------------------------------------
extern "C" void kernel_launch(void* const* d_in, const int* in_sizes, int n_in,
                              void* d_out, int out_size)
{
    const float* data = (const float*)d_in[0];
    const float* Wih0 = (const float*)d_in[1];
    const float* Whh0 = (const float*)d_in[2];
    const float* bih0 = (const float*)d_in[3];
    const float* bhh0 = (const float*)d_in[4];
    const float* Wih1 = (const float*)d_in[5];
    const float* Whh1 = (const float*)d_in[6];
    const float* bih1 = (const float*)d_in[7];
    const float* bhh1 = (const float*)d_in[8];
    const float* Wlin = (const float*)d_in[9];
    const float* blin = (const float*)d_in[10];
    const float* W1   = (const float*)d_in[11];
    const float* b1   = (const float*)d_in[12];
    const float* W2   = (const float*)d_in[13];
    const float* b2   = (const float*)d_in[14];
    const float* Wd   = (const float*)d_in[15];
    const float* bd   = (const float*)d_in[16];
    float* out = (float*)d_out;

    // Layer 0: input projection (data layout [T,G,IN]) then recurrence
    proj_kernel<<<G_ * 4, 256>>>(Wih0, bih0, bhh0, data, /*xmode=*/0, /*rows=*/H4_, /*omode=*/0);
    lstm_rec_kernel<<<G_, 1024>>>(Whh0, 0, out);

    // Layer 1: projection from h1, recurrence
    proj_kernel<<<G_ * 4, 256>>>(Wih1, bih1, bhh1, nullptr, /*xmode=*/1, H4_, 0);
    lstm_rec_kernel<<<G_, 1024>>>(Whh1, 1, out);

    // Per-group Linear
    proj_kernel<<<G_, 256>>>(Wlin, blin, nullptr, nullptr, /*xmode=*/2, /*rows=*/H_, /*omode=*/1);

    // Shared heads + softmax over groups
    heads_kernel<<<80, 256>>>(W1, b1, W2, b2, Wd, bd, out);
    softmax_kernel<<<10, 256>>>(out);
}

// round 2
// speedup vs baseline: 2.0578x; 2.0578x over previous
#include <cuda_runtime.h>
#include <cuda_bf16.h>
#include <math.h>
#include <stdint.h>

#define G_   64
#define T_   10
#define H_   256
#define H4_  1024

// Output offsets (tuple flattened: gamma, beta, delta, hN, cN)
#define OFF_GAMMA 0
#define OFF_BETA  640
#define OFF_DELTA 164480
#define OFF_HN    328320
#define OFF_CN    361088

// Scratch
__device__ float g_h1  [G_ * T_ * H_];
__device__ float g_h2  [G_ * T_ * H_];
__device__ float g_fc  [G_ * T_ * H_];
__device__ float g_lin1[G_ * T_ * H_];

__device__ __forceinline__ float sigf(float x) { return 1.0f / (1.0f + expf(-x)); }

// packed f32x2 FMA: acc += a * b (elementwise on 2 packed floats)
__device__ __forceinline__ void fma2(unsigned long long& acc, unsigned long long a, unsigned long long b) {
    asm("fma.rn.f32x2 %0, %1, %2, %0;" : "+l"(acc) : "l"(a), "l"(b));
}
__device__ __forceinline__ float unpack_sum(unsigned long long v) {
    unsigned int lo, hi;
    asm("mov.b64 {%0, %1}, %2;" : "=r"(lo), "=r"(hi) : "l"(v));
    return __uint_as_float(lo) + __uint_as_float(hi);
}
__device__ __forceinline__ unsigned int smem_u32(const void* p) {
    unsigned int a;
    asm("{ .reg .u64 t; cvta.to.shared.u64 t, %1; cvt.u32.u64 %0, t; }" : "=r"(a) : "l"(p));
    return a;
}
__device__ __forceinline__ void st_cluster_f32(unsigned int saddr, unsigned int rank, float v) {
    unsigned int r;
    asm volatile("mapa.shared::cluster.u32 %0, %1, %2;" : "=r"(r) : "r"(saddr), "r"(rank));
    asm volatile("st.shared::cluster.f32 [%0], %1;" :: "r"(r), "f"(v) : "memory");
}
#define CLUSTER_SYNC() do { \
    asm volatile("barrier.cluster.arrive.aligned;" ::: "memory"); \
    asm volatile("barrier.cluster.wait.aligned;"   ::: "memory"); } while (0)

// ---------------------------------------------------------------------------
// Fused LSTM layer: input projection (streamed) + recurrence.
// Cluster of 8 CTAs per group; CTA rank r owns hidden units [32r, 32r+32)
// -> 128 gate rows. 256 threads: thread = (row_local = tid>>1, half = tid&1).
// Whh slice lives in registers (128 floats/thread). h exchanged via DSMEM.
// Grid: 512 CTAs (= 64 groups x 8), cluster_dims 8.
// ---------------------------------------------------------------------------
__global__ void __cluster_dims__(8, 1, 1) __launch_bounds__(256, 1)
lstm_fused_kernel(const float* __restrict__ Wih, const float* __restrict__ Whh,
                  const float* __restrict__ bih, const float* __restrict__ bhh,
                  const float* __restrict__ Xin, int xmode,  // 0: data [T,G,256]; 1: g_h1
                  int layer, float* __restrict__ out)
{
    __shared__ __align__(16) float xs[T_ * 256];     // input x for this group
    __shared__ __align__(16) float h_buf[2][256];    // double-buffered hidden state
    __shared__ float gate_s[128];

    const int g    = blockIdx.x >> 3;
    const int rank = blockIdx.x & 7;
    const int tid  = threadIdx.x;
    const int row_local = tid >> 1;        // 0..127
    const int half      = tid & 1;         // column half
    const int gate    = row_local >> 5;    // 0..3 (i,f,g,o)
    const int u_local = row_local & 31;
    const int grow    = gate * 256 + rank * 32 + u_local;   // global gate row

    // ---- load x[g] into smem ----
    if (xmode == 0) {
        for (int e = tid; e < T_ * 256; e += 256) {
            int t = e >> 8, i = e & 255;
            xs[e] = Xin[((size_t)t * G_ + g) * 256 + i];
        }
    } else {
        const float* hp = g_h1 + (size_t)g * T_ * 256;
        for (int e = tid; e < T_ * 256; e += 256) xs[e] = hp[e];
    }
    if (tid < 256) { h_buf[0][tid] = 0.0f; }   // only buffer 0 needs zeros
    __syncthreads();

    // ---- input projection: xgp[t] = bias + dot(Wih[grow][half*128..], x[t][half*128..]) ----
    const float bias = (half == 0)
        ? bih[(size_t)g * H4_ + grow] + bhh[(size_t)g * H4_ + grow] : 0.0f;
    unsigned long long xa[T_], xb[T_];
    #pragma unroll
    for (int t = 0; t < T_; t++) { xa[t] = 0ull; xb[t] = 0ull; }

    const ulonglong2* Wih2 = (const ulonglong2*)(Wih + (((size_t)g * H4_ + grow) * 256 + half * 128));
    const ulonglong2* xs2  = (const ulonglong2*)xs;   // [t][64 ull2? no: 256 floats = 64 ull2]
    #pragma unroll 8
    for (int i = 0; i < 32; i++) {
        ulonglong2 w = Wih2[i];
        #pragma unroll
        for (int t = 0; t < T_; t++) {
            ulonglong2 x = xs2[t * 64 + half * 32 + i];
            fma2(xa[t], w.x, x.x);
            fma2(xb[t], w.y, x.y);
        }
    }
    float xgp[T_];
    #pragma unroll
    for (int t = 0; t < T_; t++) xgp[t] = bias + unpack_sum(xa[t]) + unpack_sum(xb[t]);

    // ---- preload Whh slice into registers ----
    ulonglong2 wreg[32];
    const ulonglong2* Whh2 = (const ulonglong2*)(Whh + (((size_t)g * H4_ + grow) * 256 + half * 128));
    #pragma unroll
    for (int i = 0; i < 32; i++) wreg[i] = Whh2[i];

    __syncthreads();
    CLUSTER_SYNC();   // all CTAs initialized before DSMEM traffic

    const unsigned int hbuf_base = smem_u32(&h_buf[0][0]);
    float* hdst = (layer == 0 ? g_h1 : g_h2) + (size_t)g * T_ * 256;

    float c_reg = 0.0f, h_last = 0.0f;
    int p = 0;

    for (int t = 0; t < T_; t++) {
        // matvec vs h_buf[p]
        const ulonglong2* h2 = (const ulonglong2*)(&h_buf[p][0]);
        unsigned long long a0 = 0ull, a1 = 0ull;
        #pragma unroll
        for (int i = 0; i < 32; i++) {
            ulonglong2 h = h2[half * 32 + i];
            fma2(a0, wreg[i].x, h.x);
            fma2(a1, wreg[i].y, h.y);
        }
        float s = unpack_sum(a0) + unpack_sum(a1) + xgp[t];
        s += __shfl_xor_sync(0xffffffffu, s, 1);
        if (half == 0) gate_s[row_local] = s;
        __syncthreads();

        if (tid < 32) {
            const int u = tid;
            float ig = gate_s[u];
            float fg = gate_s[32 + u];
            float gg = gate_s[64 + u];
            float og = gate_s[96 + u];
            c_reg = sigf(fg) * c_reg + sigf(ig) * tanhf(gg);
            float h = sigf(og) * tanhf(c_reg);
            h_last = h;
            hdst[(size_t)t * 256 + rank * 32 + u] = h;
            const unsigned int dst = hbuf_base + (unsigned)((1 - p) * 256 + rank * 32 + u) * 4u;
            #pragma unroll
            for (int pr = 0; pr < 8; pr++) st_cluster_f32(dst, (unsigned)pr, h);
        }
        CLUSTER_SYNC();   // also acts as CTA barrier: gate_s reads done, h visible
        p ^= 1;
    }

    if (tid < 32) {
        out[OFF_HN + (size_t)g * 512 + layer * 256 + rank * 32 + tid] = h_last;
        out[OFF_CN + (size_t)g * 512 + layer * 256 + rank * 32 + tid] = c_reg;
    }
}

// ---------------------------------------------------------------------------
// Per-group Linear: fc[g,t,o] = sum_h Wlin[g,o,h]*h2[g,t,h] + blin[g,o]
// Grid: G_*2 blocks, 256 threads; warp handles 16 rows x 10 t.
// ---------------------------------------------------------------------------
__global__ void wlin_kernel(const float* __restrict__ W, const float* __restrict__ b)
{
    __shared__ __align__(16) float xs[T_ * 256];
    const int g     = blockIdx.x >> 1;
    const int kbase = (blockIdx.x & 1) << 7;
    const int tid   = threadIdx.x;
    const int lane  = tid & 31;
    const int warp  = tid >> 5;

    const float* hp = g_h2 + (size_t)g * T_ * 256;
    for (int e = tid; e < T_ * 256; e += 256) xs[e] = hp[e];
    __syncthreads();

    const float4* xs4 = (const float4*)xs;
    for (int r = 0; r < 16; r++) {
        const int k = kbase + warp * 16 + r;
        const float4* wr = (const float4*)(W + ((size_t)g * 256 + k) * 256);
        float4 a0 = wr[lane];
        float4 a1 = wr[lane + 32];
        float bias = (lane == 0) ? b[(size_t)g * 256 + k] : 0.0f;
        #pragma unroll
        for (int t = 0; t < T_; t++) {
            float4 x0 = xs4[t * 64 + lane];
            float4 x1 = xs4[t * 64 + lane + 32];
            float s = a0.x * x0.x + a0.y * x0.y + a0.z * x0.z + a0.w * x0.w
                    + a1.x * x1.x + a1.y * x1.y + a1.z * x1.z + a1.w * x1.w;
            #pragma unroll
            for (int o = 16; o > 0; o >>= 1) s += __shfl_xor_sync(0xffffffffu, s, o);
            if (lane == 0) g_fc[((size_t)g * T_ + t) * 256 + k] = s + bias;
        }
    }
}

// ---------------------------------------------------------------------------
// Shared heads: lin1 / beta(softplus) / gamma.  Grid: 80 blocks x 256 thr.
// ---------------------------------------------------------------------------
__global__ void heads_kernel(const float* __restrict__ W1, const float* __restrict__ b1,
                             const float* __restrict__ W2, const float* __restrict__ b2,
                             const float* __restrict__ Wd, const float* __restrict__ bd,
                             float* __restrict__ out)
{
    __shared__ __align__(16) float fcs[8][256];
    __shared__ float red[256];

    const int t  = blockIdx.x % 10;
    const int g0 = (blockIdx.x / 10) * 8;
    const int j  = threadIdx.x;

    for (int gg = 0; gg < 8; gg++)
        fcs[gg][j] = g_fc[((size_t)(g0 + gg) * T_ + t) * 256 + j];
    __syncthreads();

    const float4* w1r = (const float4*)(W1 + (size_t)j * 256);
    const float4* w2r = (const float4*)(W2 + (size_t)j * 256);
    const float4 (*f4)[64] = (const float4 (*)[64])fcs;

    float acc1[8], acc2[8];
    #pragma unroll
    for (int gg = 0; gg < 8; gg++) { acc1[gg] = b1[j]; acc2[gg] = b2[j]; }

    #pragma unroll 4
    for (int i4 = 0; i4 < 64; i4++) {
        float4 w1 = w1r[i4];
        float4 w2 = w2r[i4];
        #pragma unroll
        for (int gg = 0; gg < 8; gg++) {
            float4 f = f4[gg][i4];
            acc1[gg] += w1.x * f.x + w1.y * f.y + w1.z * f.z + w1.w * f.w;
            acc2[gg] += w2.x * f.x + w2.y * f.y + w2.z * f.z + w2.w * f.w;
        }
    }

    const float wd = Wd[j];
    #pragma unroll
    for (int gg = 0; gg < 8; gg++) {
        const size_t idx = ((size_t)(g0 + gg) * T_ + t) * 256 + j;
        g_lin1[idx] = acc1[gg];
        float x = acc2[gg];
        out[OFF_BETA + idx] = (x > 20.0f) ? x : log1pf(expf(x));
    }

    for (int gg = 0; gg < 8; gg++) {
        red[j] = acc1[gg] * wd;
        __syncthreads();
        #pragma unroll
        for (int s = 128; s > 0; s >>= 1) {
            if (j < s) red[j] += red[j + s];
            __syncthreads();
        }
        if (j == 0) out[OFF_GAMMA + (size_t)(g0 + gg) * T_ + t] = red[0] + bd[0];
        __syncthreads();
    }
}

// ---------------------------------------------------------------------------
// Softmax over groups. Grid: 10 blocks x 256 threads.
// ---------------------------------------------------------------------------
__global__ void softmax_kernel(float* __restrict__ out)
{
    const int t = blockIdx.x;
    const int j = threadIdx.x;

    float v[G_];
    float m = -1e30f;
    #pragma unroll
    for (int g = 0; g < G_; g++) {
        v[g] = g_lin1[((size_t)g * T_ + t) * 256 + j];
        m = fmaxf(m, v[g]);
    }
    float s = 0.0f;
    #pragma unroll
    for (int g = 0; g < G_; g++) { v[g] = expf(v[g] - m); s += v[g]; }
    const float inv = 1.0f / s;
    #pragma unroll
    for (int g = 0; g < G_; g++)
        out[OFF_DELTA + ((size_t)g * T_ + t) * 256 + j] = v[g] * inv;
}

// ---------------------------------------------------------------------------
extern "C" void kernel_launch(void* const* d_in, const int* in_sizes, int n_in,
                              void* d_out, int out_size)
{
    const float* data = (const float*)d_in[0];
    const float* Wih0 = (const float*)d_in[1];
    const float* Whh0 = (const float*)d_in[2];
    const float* bih0 = (const float*)d_in[3];
    const float* bhh0 = (const float*)d_in[4];
    const float* Wih1 = (const float*)d_in[5];
    const float* Whh1 = (const float*)d_in[6];
    const float* bih1 = (const float*)d_in[7];
    const float* bhh1 = (const float*)d_in[8];
    const float* Wlin = (const float*)d_in[9];
    const float* blin = (const float*)d_in[10];
    const float* W1   = (const float*)d_in[11];
    const float* b1   = (const float*)d_in[12];
    const float* W2   = (const float*)d_in[13];
    const float* b2   = (const float*)d_in[14];
    const float* Wd   = (const float*)d_in[15];
    const float* bd   = (const float*)d_in[16];
    float* out = (float*)d_out;

    lstm_fused_kernel<<<G_ * 8, 256>>>(Wih0, Whh0, bih0, bhh0, data, 0, 0, out);
    lstm_fused_kernel<<<G_ * 8, 256>>>(Wih1, Whh1, bih1, bhh1, nullptr, 1, 1, out);
    wlin_kernel<<<G_ * 2, 256>>>(Wlin, blin);
    heads_kernel<<<80, 256>>>(W1, b1, W2, b2, Wd, bd, out);
    softmax_kernel<<<10, 256>>>(out);
}